// round 10
// baseline (speedup 1.0000x reference)
#include <cuda_runtime.h>
#include <cstdint>
#include <math_constants.h>

// OpeningLoss2D: mean((x - grey_opening_2x2(x))^2) over [8,16,512,512] fp32.
// Separable hmin2 -> vmin2 -> hmax2 -> vmax2 (scipy w=2, edge replicate,
// er-index clamps on dilation).
//
// Same tile plan as R9 (best): 1024 blocks, 512x64 tiles, cp.async ring of
// 8 row slots, 2 rows/group, 3 groups in flight, interior-tile clamp-free
// specialization. This round: 256 threads/block, 2 cols/thread (cp.async.ca.8)
// => 8 warps/block, ~2x resident warps at identical traffic/smem.

#define FULLMASK 0xffffffffu

static const int Hc = 512;
static const int Wc = 512;
static const int TR = 64;
static const int NBLK = 1024;          // 128 slices * 8 row-tiles
static const int ROWP = 520;           // slot stride (floats), 16B aligned

__device__ float g_partials[NBLK];
__device__ unsigned int g_count = 0;

__device__ __forceinline__ void cp_async8(uint32_t saddr, const float* gaddr) {
    asm volatile("cp.async.ca.shared.global [%0], [%1], 8;\n"
                 :: "r"(saddr), "l"(gaddr));
}
__device__ __forceinline__ void cp_commit() {
    asm volatile("cp.async.commit_group;\n" ::: "memory");
}
template <int N>
__device__ __forceinline__ void cp_wait() {
    asm volatile("cp.async.wait_group %0;\n" :: "n"(N) : "memory");
}

// One 512x64 tile; returns this thread's squared-error partial.
// INTERIOR: r0 in [64, 384] -> no row clamps (incl. overrun groups <= r0+68).
template <bool INTERIOR>
__device__ __forceinline__ float process_tile(
    const float* __restrict__ S, float (*ring)[ROWP], uint32_t sring,
    int r0, int c0, bool isL0, bool isL31, int lcol, int rcol)
{
    const float* gp = S + (size_t)(INTERIOR ? (r0 - 1) : 0) * Wc + c0;

    #define ISSUE2(g) do {                                                    \
        int _p0 = 2 * (g);                                                    \
        if (INTERIOR) {                                                       \
            cp_async8(sring + (uint32_t)((( _p0)     & 7) * (ROWP * 4)),      \
                      gp + (size_t)_p0 * Wc);                                 \
            cp_async8(sring + (uint32_t)(((_p0 + 1) & 7) * (ROWP * 4)),       \
                      gp + (size_t)(_p0 + 1) * Wc);                           \
        } else {                                                              \
            int _g0 = min(max(r0 - 1 + _p0, 0), Hc - 1);                      \
            int _g1 = min(r0 + _p0, Hc - 1);                                  \
            cp_async8(sring + (uint32_t)((( _p0)     & 7) * (ROWP * 4)),      \
                      S + (size_t)_g0 * Wc + c0);                             \
            cp_async8(sring + (uint32_t)(((_p0 + 1) & 7) * (ROWP * 4)),       \
                      S + (size_t)_g1 * Wc + c0);                             \
        }                                                                     \
    } while (0)

    #define LOADROW(pp)                                                       \
        const float* _row = &ring[(pp) & 7][0];                               \
        float2 _q = *reinterpret_cast<const float2*>(_row + c0);              \
        float _L = __shfl_up_sync(FULLMASK, _q.y, 1);                         \
        float _R = __shfl_down_sync(FULLMASK, _q.x, 1);                       \
        if (isL0)  _L = _row[lcol];                                           \
        if (isL31) _R = _row[rcol];                                           \
        float _h0 = fminf(_L,  _q.x);                                         \
        float _h1 = fminf(_q.x, _q.y);                                        \
        float _h2 = fminf(_q.y, _R);

    #define FULLROW(pp) do {                                                  \
        LOADROW(pp)                                                            \
        float _e0 = fminf(hp0,_h0), _e1 = fminf(hp1,_h1), _e2 = fminf(hp2,_h2);\
        float _M0 = fmaxf(_e0,_e1), _M1 = fmaxf(_e1,_e2);                      \
        float _s0 = fmaxf(Mp0,_M0), _s1 = fmaxf(Mp1,_M1);                      \
        float _d0 = xp0 - _s0, _d1 = xp1 - _s1;                                \
        acc0 = fmaf(_d0,_d0,acc0); acc1 = fmaf(_d1,_d1,acc1);                  \
        hp0=_h0; hp1=_h1; hp2=_h2;                                             \
        Mp0=_M0; Mp1=_M1;                                                      \
        xp0=_q.x; xp1=_q.y;                                                    \
    } while (0)

    float hp0, hp1, hp2;
    float Mp0, Mp1;
    float xp0, xp1;
    float acc0 = 0.f, acc1 = 0.f;

    #pragma unroll
    for (int g = 0; g < 3; ++g) { ISSUE2(g); cp_commit(); }

    // step 0 (rows 0,1) peeled: no er at p=0, no smooth at p=1
    cp_wait<2>();
    __syncthreads();
    ISSUE2(3);
    cp_commit();
    {   LOADROW(0)
        hp0=_h0; hp1=_h1; hp2=_h2;
    }
    {   LOADROW(1)
        float _e0 = fminf(hp0,_h0), _e1 = fminf(hp1,_h1), _e2 = fminf(hp2,_h2);
        Mp0 = fmaxf(_e0,_e1); Mp1 = fmaxf(_e1,_e2);
        hp0=_h0; hp1=_h1; hp2=_h2;
        xp0=_q.x; xp1=_q.y;
    }

    // hot loop: steps 1..31 (rows 2..63); overrun groups write slots consumed
    // >= 2 steps earlier (same safety argument as R5/R9).
    #pragma unroll 4
    for (int s = 1; s <= 31; ++s) {
        cp_wait<2>();
        __syncthreads();
        ISSUE2(s + 3);
        cp_commit();
        FULLROW(2 * s);
        FULLROW(2 * s + 1);
    }

    // step 32 (rows 64,65): bottom boundary
    cp_wait<0>();
    __syncthreads();
    FULLROW(64);
    if (INTERIOR || r0 + TR < Hc) {
        FULLROW(65);
    } else {
        // er row 512 doesn't exist: smooth(511) = hM(511) = Mp
        float _d0 = xp0 - Mp0, _d1 = xp1 - Mp1;
        acc0 = fmaf(_d0,_d0,acc0); acc1 = fmaf(_d1,_d1,acc1);
    }
    #undef ISSUE2
    #undef LOADROW
    #undef FULLROW

    return acc0 + acc1;
}

__global__ void __launch_bounds__(256, 6)
opening_kernel(const float* __restrict__ X, float* __restrict__ out) {
    __shared__ float ring[8][ROWP];       // 16.6 KB; data [0..511], sentinel 512
    __shared__ float wsum[8];
    __shared__ bool amLast;

    const int t      = threadIdx.x;       // 0..255
    const int lane   = t & 31;
    const int warpId = t >> 5;
    const int tile   = blockIdx.x;        // 0..1023
    const int slice  = tile >> 3;         // 0..127
    const int r0     = (tile & 7) * TR;
    const float* S   = X + (size_t)slice * (Hc * Wc);
    const int c0     = t << 1;            // first owned column (0..510)
    const bool isL0  = (lane == 0);
    const bool isL31 = (lane == 31);
    const int lcol   = max(c0 - 1, 0);    // left clamp (t=0 -> col 0)
    const int rcol   = c0 + 2;            // t=255 -> col 512 = -inf sentinel

    if (t < 8) ring[t][512] = -CUDART_INF_F;

    const uint32_t sring =
        (uint32_t)__cvta_generic_to_shared(&ring[0][0]) + (uint32_t)(c0 * 4);

    const bool interior = (r0 != 0) && (r0 != (Hc - TR));
    float acc = interior
        ? process_tile<true >(S, ring, sring, r0, c0, isL0, isL31, lcol, rcol)
        : process_tile<false>(S, ring, sring, r0, c0, isL0, isL31, lcol, rcol);

    #pragma unroll
    for (int off = 16; off; off >>= 1)
        acc += __shfl_down_sync(FULLMASK, acc, off);
    if (lane == 0) wsum[warpId] = acc;
    __syncthreads();
    if (t == 0) {
        float s = 0.f;
        #pragma unroll
        for (int i = 0; i < 8; ++i) s += wsum[i];
        g_partials[blockIdx.x] = s;
        __threadfence();
        unsigned int old = atomicAdd(&g_count, 1u);
        amLast = (old == (unsigned)(NBLK - 1));
    }
    __syncthreads();

    if (amLast) {
        __shared__ float sh[256];
        float s = 0.f;
        for (int i = t; i < NBLK; i += 256) s += g_partials[i];
        sh[t] = s;
        __syncthreads();
        #pragma unroll
        for (int off = 128; off; off >>= 1) {
            if (t < off) sh[t] += sh[t + off];
            __syncthreads();
        }
        if (t == 0) {
            out[0] = sh[0] * (1.0f / 33554432.0f);  // mean over 8*16*512*512
            g_count = 0;                            // deterministic replays
        }
    }
}

extern "C" void kernel_launch(void* const* d_in, const int* in_sizes, int n_in,
                              void* d_out, int out_size) {
    const float* X = (const float*)d_in[0];
    opening_kernel<<<NBLK, 256>>>(X, (float*)d_out);
}